// round 13
// baseline (speedup 1.0000x reference)
#include <cuda_runtime.h>
#include <cuda_fp16.h>
#include <cstdint>

#define W_DIM 81920
#define N_DIM 4
#define C_DIM 64
#define O_DIM 64
#define K_DIM 10
#define TILE_W 128
#define TILES_PER_N (W_DIM / TILE_W)            // 640
#define NTILES      (N_DIM * TILES_PER_N)       // 2560
#define TBL_ELEMS   (W_DIM * K_DIM)             // 819200
#define PHASES 10
#define NSTAGE 4
#define PITCHB 144                              // 128B row + 16B pad
#define A_BYTES (TILE_W * PITCHB)               // 18432
#define B_BYTES (O_DIM * PITCHB)                // 9216
#define STAGE_BYTES (A_BYTES + B_BYTES)         // 27648
#define SM_BIAS 0
#define SM_STAGE 256
#define SMEM_BYTES (SM_STAGE + NSTAGE * STAGE_BYTES)  // 110848

// Static device scratch (no runtime allocation)
__device__ __half g_xH[(size_t)N_DIM * W_DIM * C_DIM];  // [N,W,C] fp16
__device__ __half g_wH[K_DIM * O_DIM * C_DIM];          // [k][o][c] fp16
__device__ int    g_idxT[TBL_ELEMS];                    // gather table [k][w]
__device__ int    g_is_i32;

// ---------------------------------------------------------------------------
__global__ void detect_kernel(const int* __restrict__ t32) {
    __shared__ int f;
    if (threadIdx.x == 0) f = 0;
    __syncthreads();
    if (t32[2 * threadIdx.x + 1] != 0) atomicOr(&f, 1);
    __syncthreads();
    if (threadIdx.x == 0) g_is_i32 = f;
}

__global__ void convert_kernel(const int* __restrict__ t32) {
    int i = blockIdx.x * 256 + threadIdx.x;
    if (i < TBL_ELEMS) {
        int v = g_is_i32 ? t32[i] : t32[2 * i];
        int w = i / K_DIM;
        int k = i - w * K_DIM;
        g_idxT[k * W_DIM + w] = v;
    }
}

// input [N,C,W] -> g_xH [N,W,C] (fp16, half2 stores)
__global__ void transpose_kernel(const float* __restrict__ in) {
    __shared__ float t[32][33];
    int n  = blockIdx.z;
    int c0 = blockIdx.y << 5;
    int w0 = blockIdx.x << 5;
    int tx = threadIdx.x, ty = threadIdx.y;

    const size_t inb = ((size_t)n * C_DIM + c0) * W_DIM + w0;
#pragma unroll
    for (int i = 0; i < 32; i += 8)
        t[ty + i][tx] = in[inb + (size_t)(ty + i) * W_DIM + tx];
    __syncthreads();

    int id = ty * 32 + tx;          // 0..255
    int cp = id & 15;               // c-pair
    int wl = id >> 4;               // 0..15
    const size_t ob = ((size_t)n * W_DIM + w0) * C_DIM + c0;
#pragma unroll
    for (int i = 0; i < 2; ++i) {
        int w = wl + 16 * i;
        __half2 h = __floats2half2_rn(t[2 * cp][w], t[2 * cp + 1][w]);
        *reinterpret_cast<__half2*>(&g_xH[ob + (size_t)w * C_DIM + 2 * cp]) = h;
    }
}

// weight [O,C,K,1] -> g_wH [k][o][c] (fp16)
__global__ void wprep_kernel(const float* __restrict__ w) {
    int i = blockIdx.x * 256 + threadIdx.x;
    if (i < O_DIM * C_DIM * K_DIM) {
        int o = i / (C_DIM * K_DIM);
        int r = i - o * (C_DIM * K_DIM);
        int c = r / K_DIM;
        int k = r - c * K_DIM;
        g_wH[(k * O_DIM + o) * C_DIM + c] = __float2half(w[i]);
    }
}

// ---------------------------------------------------------------------------
// Conv: tile 128w x 64o, 4-stage cp.async pipeline with continuous cross-tile
// issuing, fp16 mma.sync m16n8k16 f32-accum. 8 warps 4(m) x 2(n), 32x32 each.
// ---------------------------------------------------------------------------
__global__ void __launch_bounds__(256, 2)
conv_kernel(const float* __restrict__ bias, float* __restrict__ out) {
    extern __shared__ char smem[];
    const unsigned sb = (unsigned)__cvta_generic_to_shared(smem);

    const int tid  = threadIdx.x;
    const int wid  = tid >> 5;
    const int lane = tid & 31;
    const int wr   = wid >> 1;          // warp row 0..3 (m offset 32*wr)
    const int wn   = wid & 1;           // warp col 0..1 (n offset 32*wn)

    if (tid < O_DIM)
        *reinterpret_cast<float*>(smem + SM_BIAS + tid * 4) = bias[tid];

    // ldmatrix per-lane source offsets (within a stage)
    const int lr = lane & 7;
    const int lm = lane >> 3;
    unsigned aoff[2];
#pragma unroll
    for (int mt = 0; mt < 2; ++mt)      // A x4: {m-lo k-lo, m-hi k-lo, m-lo k-hi, m-hi k-hi}
        aoff[mt] = (unsigned)((wr * 32 + mt * 16 + (lm & 1) * 8 + lr) * PITCHB
                              + (lm >> 1) * 16);
    unsigned boff[2];
#pragma unroll
    for (int bp = 0; bp < 2; ++bp)      // B x4: {n-lo k-lo, n-lo k-hi, n-hi k-lo, n-hi k-hi}
        boff[bp] = (unsigned)(A_BYTES
                              + (wn * 32 + bp * 16 + (lm >> 1) * 8 + lr) * PITCHB
                              + (lm & 1) * 16);

    const int g2 = lane >> 2;           // epilogue C-layout row
    const int tg = lane & 3;            // epilogue C-layout col pair

    const int arow = tid >> 3;          // loader: A row base (0..31)
    const int ac8  = tid & 7;           // loader: 16B chunk in row
    __syncthreads();

    // issue phase p of tile with given params into stage s
    auto issue = [&](const __half* xb, int w0_, int p, int s) {
        const unsigned stg = sb + SM_STAGE + (unsigned)s * STAGE_BYTES;
        const int* idxp = g_idxT + p * W_DIM + w0_;
#pragma unroll
        for (int j = 0; j < 4; ++j) {               // A: 1024 16B chunks
            int row = arow + 32 * j;
            int idx = idxp[row];
            unsigned sa = stg + (unsigned)(row * PITCHB + ac8 * 16);
            const __half* ga = xb + (size_t)idx * C_DIM + ac8 * 8;
            asm volatile("cp.async.cg.shared.global [%0], [%1], 16;"
                         :: "r"(sa), "l"(ga) : "memory");
        }
        const __half* wp = g_wH + p * (O_DIM * C_DIM);
#pragma unroll
        for (int j = 0; j < 2; ++j) {               // B: 512 16B chunks
            int lin = tid + 256 * j;
            int o   = lin >> 3;
            int c8  = lin & 7;
            unsigned sa = stg + (unsigned)(A_BYTES + o * PITCHB + c8 * 16);
            asm volatile("cp.async.cg.shared.global [%0], [%1], 16;"
                         :: "r"(sa), "l"(wp + o * C_DIM + c8 * 8) : "memory");
        }
        asm volatile("cp.async.commit_group;" ::: "memory");
    };

    // current-tile params
    int t  = blockIdx.x;
    int n  = t / TILES_PER_N;
    int w0 = (t - n * TILES_PER_N) * TILE_W;
    const __half* xHn = g_xH + (size_t)n * W_DIM * C_DIM;

    // prologue: first 3 phases of first tile (stages 0,1,2)
    issue(xHn, w0, 0, 0);
    issue(xHn, w0, 1, 1);
    issue(xHn, w0, 2, 2);

    int tc = 0;                          // tile counter: stage base = (2*tc)&3
    for (; t < NTILES; t += gridDim.x, ++tc) {
        // next-tile params (clamped dummy for the last tile)
        int t2  = t + gridDim.x; if (t2 >= NTILES) t2 = NTILES - 1;
        int n2  = t2 / TILES_PER_N;
        int w02 = (t2 - n2 * TILES_PER_N) * TILE_W;
        const __half* xHn2 = g_xH + (size_t)n2 * W_DIM * C_DIM;

        float acc[2][4][4];
#pragma unroll
        for (int mt = 0; mt < 2; ++mt)
#pragma unroll
            for (int nt = 0; nt < 4; ++nt)
#pragma unroll
                for (int r = 0; r < 4; ++r) acc[mt][nt][r] = 0.0f;

        const int base2 = 2 * tc;        // stage base (mod 4)

        for (int p = 0; p < PHASES; ++p) {
            asm volatile("cp.async.wait_group 2;" ::: "memory");
            __syncthreads();             // group for phase p complete; prior reads done

            const unsigned stg = sb + SM_STAGE
                               + (unsigned)((base2 + p) & 3) * STAGE_BYTES;
#pragma unroll
            for (int kk = 0; kk < 4; ++kk) {        // k16 steps
                const unsigned kb = kk * 32;
                uint32_t a[2][4], b[4][2];
#pragma unroll
                for (int mt = 0; mt < 2; ++mt)
                    asm volatile(
                        "ldmatrix.sync.aligned.m8n8.x4.shared.b16 {%0,%1,%2,%3}, [%4];"
                        : "=r"(a[mt][0]), "=r"(a[mt][1]), "=r"(a[mt][2]), "=r"(a[mt][3])
                        : "r"(stg + aoff[mt] + kb));
#pragma unroll
                for (int bp = 0; bp < 2; ++bp)
                    asm volatile(
                        "ldmatrix.sync.aligned.m8n8.x4.shared.b16 {%0,%1,%2,%3}, [%4];"
                        : "=r"(b[2 * bp][0]), "=r"(b[2 * bp][1]),
                          "=r"(b[2 * bp + 1][0]), "=r"(b[2 * bp + 1][1])
                        : "r"(stg + boff[bp] + kb));
#pragma unroll
                for (int mt = 0; mt < 2; ++mt)
#pragma unroll
                    for (int nt = 0; nt < 4; ++nt)
                        asm volatile(
                            "mma.sync.aligned.m16n8k16.row.col.f32.f16.f16.f32 "
                            "{%0,%1,%2,%3}, {%4,%5,%6,%7}, {%8,%9}, {%0,%1,%2,%3};"
                            : "+f"(acc[mt][nt][0]), "+f"(acc[mt][nt][1]),
                              "+f"(acc[mt][nt][2]), "+f"(acc[mt][nt][3])
                            : "r"(a[mt][0]), "r"(a[mt][1]), "r"(a[mt][2]), "r"(a[mt][3]),
                              "r"(b[nt][0]), "r"(b[nt][1]));
            }

            // continuous issuing: phase p+3 (this tile or next tile's p+3-10)
            int q = p + 3;
            int s = (base2 + q) & 3;
            if (q < PHASES) issue(xHn, w0, q, s);
            else            issue(xHn2, w02, q - PHASES, s);
        }

        // ---- epilogue: bias + relu + store ----
        const float* sbias = reinterpret_cast<const float*>(smem + SM_BIAS);
#pragma unroll
        for (int nt = 0; nt < 4; ++nt) {
            const int o0 = wn * 32 + nt * 8 + 2 * tg;
            const float bz0 = sbias[o0], bz1 = sbias[o0 + 1];
            const size_t ob0 = ((size_t)n * O_DIM + o0) * W_DIM + w0;
            const size_t ob1 = ob0 + W_DIM;
#pragma unroll
            for (int mt = 0; mt < 2; ++mt) {
                const int wrow = wr * 32 + mt * 16 + g2;
                out[ob0 + wrow]     = fmaxf(acc[mt][nt][0] + bz0, 0.0f);
                out[ob1 + wrow]     = fmaxf(acc[mt][nt][1] + bz1, 0.0f);
                out[ob0 + wrow + 8] = fmaxf(acc[mt][nt][2] + bz0, 0.0f);
                out[ob1 + wrow + 8] = fmaxf(acc[mt][nt][3] + bz1, 0.0f);
            }
        }

        // advance current-tile params
        n = n2; w0 = w02; xHn = xHn2;
    }

    // drain outstanding async copies before exit
    asm volatile("cp.async.wait_group 0;" ::: "memory");
    __syncthreads();
}

// ---------------------------------------------------------------------------
extern "C" void kernel_launch(void* const* d_in, const int* in_sizes, int n_in,
                              void* d_out, int out_size) {
    const float* input  = (const float*)d_in[0];
    const int*   tbl32  = (const int*)d_in[1];
    const float* weight = (const float*)d_in[2];
    const float* bias   = (const float*)d_in[3];
    float*       out    = (float*)d_out;

    cudaFuncSetAttribute(conv_kernel,
                         cudaFuncAttributeMaxDynamicSharedMemorySize, SMEM_BYTES);

    int dev = 0;
    cudaGetDevice(&dev);
    int nsm = 148;
    cudaDeviceGetAttribute(&nsm, cudaDevAttrMultiProcessorCount, dev);

    detect_kernel<<<1, 64>>>(tbl32);
    convert_kernel<<<(TBL_ELEMS + 255) / 256, 256>>>(tbl32);
    transpose_kernel<<<dim3(W_DIM / 32, C_DIM / 32, N_DIM), dim3(32, 8)>>>(input);
    wprep_kernel<<<(O_DIM * C_DIM * K_DIM + 255) / 256, 256>>>(weight);
    conv_kernel<<<2 * nsm, 256, SMEM_BYTES>>>(bias, out);
}

// round 14
// speedup vs baseline: 1.1519x; 1.1519x over previous
#include <cuda_runtime.h>
#include <cuda_fp16.h>
#include <cstdint>

#define W_DIM 81920
#define N_DIM 4
#define C_DIM 64
#define O_DIM 64
#define K_DIM 10
#define TILE_W 128
#define TILES_PER_N (W_DIM / TILE_W)            // 640
#define NTILES      (N_DIM * TILES_PER_N)       // 2560
#define TBL_ELEMS   (W_DIM * K_DIM)             // 819200
#define PHASES 10
#define A_STAGE 16384                           // 128 rows x 128 B, swizzled
#define WOFF    (2 * A_STAGE)                   // weights at 32768
#define W_SLICE 8192                            // 64 rows x 128 B per k
#define SMEM_BYTES (WOFF + K_DIM * W_SLICE)     // 114688

// Static device scratch (no runtime allocation)
__device__ __half g_xH[(size_t)N_DIM * W_DIM * C_DIM];  // [N,W,C] fp16
__device__ __half g_wH[K_DIM * O_DIM * C_DIM];          // [k][o][c] fp16
__device__ int    g_idxT[TBL_ELEMS];                    // gather table [k][w]
__device__ int    g_is_i32;

// ---------------------------------------------------------------------------
__global__ void detect_kernel(const int* __restrict__ t32) {
    __shared__ int f;
    if (threadIdx.x == 0) f = 0;
    __syncthreads();
    if (t32[2 * threadIdx.x + 1] != 0) atomicOr(&f, 1);
    __syncthreads();
    if (threadIdx.x == 0) g_is_i32 = f;
}

__global__ void convert_kernel(const int* __restrict__ t32) {
    int i = blockIdx.x * 256 + threadIdx.x;
    if (i < TBL_ELEMS) {
        int v = g_is_i32 ? t32[i] : t32[2 * i];
        int w = i / K_DIM;
        int k = i - w * K_DIM;
        g_idxT[k * W_DIM + w] = v;
    }
}

// input [N,C,W] -> g_xH [N,W,C] (fp16, half2 stores)
__global__ void transpose_kernel(const float* __restrict__ in) {
    __shared__ float t[32][33];
    int n  = blockIdx.z;
    int c0 = blockIdx.y << 5;
    int w0 = blockIdx.x << 5;
    int tx = threadIdx.x, ty = threadIdx.y;

    const size_t inb = ((size_t)n * C_DIM + c0) * W_DIM + w0;
#pragma unroll
    for (int i = 0; i < 32; i += 8)
        t[ty + i][tx] = in[inb + (size_t)(ty + i) * W_DIM + tx];
    __syncthreads();

    int id = ty * 32 + tx;          // 0..255
    int cp = id & 15;               // c-pair
    int wl = id >> 4;               // 0..15
    const size_t ob = ((size_t)n * W_DIM + w0) * C_DIM + c0;
#pragma unroll
    for (int i = 0; i < 2; ++i) {
        int w = wl + 16 * i;
        __half2 h = __floats2half2_rn(t[2 * cp][w], t[2 * cp + 1][w]);
        *reinterpret_cast<__half2*>(&g_xH[ob + (size_t)w * C_DIM + 2 * cp]) = h;
    }
}

// weight [O,C,K,1] -> g_wH [k][o][c] (fp16)
__global__ void wprep_kernel(const float* __restrict__ w) {
    int i = blockIdx.x * 256 + threadIdx.x;
    if (i < O_DIM * C_DIM * K_DIM) {
        int o = i / (C_DIM * K_DIM);
        int r = i - o * (C_DIM * K_DIM);
        int c = r / K_DIM;
        int k = r - c * K_DIM;
        g_wH[(k * O_DIM + o) * C_DIM + c] = __float2half(w[i]);
    }
}

// ---------------------------------------------------------------------------
// Conv: tile 128w x 64o. Weights (80KB fp16, all k) resident in smem, XOR-
// swizzled 128B rows. A double-buffered 2x16KB swizzled stages via cp.async.
// fp16 mma.sync m16n8k16 f32-accum; 8 warps 4(m) x 2(n), warp tile 32x32.
// ---------------------------------------------------------------------------
__global__ void __launch_bounds__(256, 2)
conv_kernel(const float* __restrict__ bias, float* __restrict__ out) {
    extern __shared__ char smem[];
    const unsigned sb = (unsigned)__cvta_generic_to_shared(smem);

    const int tid  = threadIdx.x;
    const int wid  = tid >> 5;
    const int lane = tid & 31;
    const int wr   = wid >> 1;          // warp row 0..3 (m offset 32*wr)
    const int wn   = wid & 1;           // warp col 0..1 (n offset 32*wn)

    // fragment row/chunk algebra (validated in R12, swizzle substituted)
    const int lr  = lane & 7;
    const int lm  = lane >> 3;
    const int ach = lm >> 1;            // A logical chunk base (16B units)
    const int bch = lm & 1;             // B logical chunk base
    unsigned arb[2]; int ars[2];        // A row-base bytes, row&7
#pragma unroll
    for (int mt = 0; mt < 2; ++mt) {
        int row = wr * 32 + mt * 16 + (lm & 1) * 8 + lr;
        arb[mt] = (unsigned)(row << 7);
        ars[mt] = row & 7;
    }
    unsigned brb[2]; int brs[2];        // B row-base (within k-slice), row&7
#pragma unroll
    for (int bp = 0; bp < 2; ++bp) {
        int row = wn * 32 + bp * 16 + (lm >> 1) * 8 + lr;
        brb[bp] = (unsigned)(WOFF + (row << 7));
        brs[bp] = row & 7;
    }

    const int g2 = lane >> 2;           // epilogue C-layout row
    const int tg = lane & 3;            // epilogue C-layout col pair

    // ---- one-time weight load: 5120 16B chunks, swizzled ----
#pragma unroll
    for (int it = 0; it < 20; ++it) {
        int lin = tid + 256 * it;       // 0..5119
        int row = lin >> 3;             // 0..639 (= k*64 + o)
        int c   = lin & 7;
        unsigned dst = sb + (unsigned)(WOFF + (row << 7) + ((c ^ (row & 7)) << 4));
        const __half* src = g_wH + (row << 6) + c * 8;
        asm volatile("cp.async.cg.shared.global [%0], [%1], 16;"
                     :: "r"(dst), "l"(src) : "memory");
    }
    asm volatile("cp.async.commit_group;" ::: "memory");

    const int arow = tid >> 3;          // loader: A row base (0..31)
    const int ac8  = tid & 7;           // loader: 16B chunk
    const int axor = (arow & 7);        // loader swizzle (const per thread)

    // issue phase p of a tile into stage (p&1)  [10 even -> parity continuous]
    auto issue = [&](const __half* xb, int w0_, int p) {
        const unsigned stg = sb + (unsigned)((p & 1) * A_STAGE);
        const int* idxp = g_idxT + p * W_DIM + w0_;
        const unsigned soff = (unsigned)((ac8 ^ axor) << 4);
#pragma unroll
        for (int j = 0; j < 4; ++j) {   // 1024 16B chunks
            int row = arow + 32 * j;
            int idx = idxp[row];
            unsigned sa = stg + (unsigned)(row << 7) + soff;
            const __half* ga = xb + (size_t)idx * C_DIM + ac8 * 8;
            asm volatile("cp.async.cg.shared.global [%0], [%1], 16;"
                         :: "r"(sa), "l"(ga) : "memory");
        }
        asm volatile("cp.async.commit_group;" ::: "memory");
    };

    // current-tile params
    int t  = blockIdx.x;
    int n  = t / TILES_PER_N;
    int w0 = (t - n * TILES_PER_N) * TILE_W;
    const __half* xHn = g_xH + (size_t)n * W_DIM * C_DIM;

    issue(xHn, w0, 0);
    issue(xHn, w0, 1);

    for (; t < NTILES; t += gridDim.x) {
        int t2  = t + gridDim.x; if (t2 >= NTILES) t2 = NTILES - 1;
        int n2  = t2 / TILES_PER_N;
        int w02 = (t2 - n2 * TILES_PER_N) * TILE_W;
        const __half* xHn2 = g_xH + (size_t)n2 * W_DIM * C_DIM;

        float acc[2][4][4];
#pragma unroll
        for (int mt = 0; mt < 2; ++mt)
#pragma unroll
            for (int nt = 0; nt < 4; ++nt)
#pragma unroll
                for (int r = 0; r < 4; ++r) acc[mt][nt][r] = 0.0f;

        for (int p = 0; p < PHASES; ++p) {
            asm volatile("cp.async.wait_group 1;" ::: "memory");
            __syncthreads();            // phase-p stage complete; prior reads done

            const unsigned stg  = sb + (unsigned)((p & 1) * A_STAGE);
            const unsigned wslc = (unsigned)(p * W_SLICE);
#pragma unroll
            for (int kk = 0; kk < 4; ++kk) {       // k16 steps
                uint32_t a[2][4], b[4][2];
#pragma unroll
                for (int mt = 0; mt < 2; ++mt) {
                    unsigned ad = stg + arb[mt]
                                + (unsigned)((((ach + 2 * kk) ^ ars[mt])) << 4);
                    asm volatile(
                        "ldmatrix.sync.aligned.m8n8.x4.shared.b16 {%0,%1,%2,%3}, [%4];"
                        : "=r"(a[mt][0]), "=r"(a[mt][1]), "=r"(a[mt][2]), "=r"(a[mt][3])
                        : "r"(ad));
                }
#pragma unroll
                for (int bp = 0; bp < 2; ++bp) {
                    unsigned bd = sb + brb[bp] + wslc
                                + (unsigned)((((bch + 2 * kk) ^ brs[bp])) << 4);
                    asm volatile(
                        "ldmatrix.sync.aligned.m8n8.x4.shared.b16 {%0,%1,%2,%3}, [%4];"
                        : "=r"(b[2 * bp][0]), "=r"(b[2 * bp][1]),
                          "=r"(b[2 * bp + 1][0]), "=r"(b[2 * bp + 1][1])
                        : "r"(bd));
                }
#pragma unroll
                for (int mt = 0; mt < 2; ++mt)
#pragma unroll
                    for (int nt = 0; nt < 4; ++nt)
                        asm volatile(
                            "mma.sync.aligned.m16n8k16.row.col.f32.f16.f16.f32 "
                            "{%0,%1,%2,%3}, {%4,%5,%6,%7}, {%8,%9}, {%0,%1,%2,%3};"
                            : "+f"(acc[mt][nt][0]), "+f"(acc[mt][nt][1]),
                              "+f"(acc[mt][nt][2]), "+f"(acc[mt][nt][3])
                            : "r"(a[mt][0]), "r"(a[mt][1]), "r"(a[mt][2]), "r"(a[mt][3]),
                              "r"(b[nt][0]), "r"(b[nt][1]));
            }

            // issue phase p+2 (this tile, or next tile's p-8); stage = just-read
            int q = p + 2;
            if (q < PHASES) issue(xHn, w0, q);
            else            issue(xHn2, w02, q - PHASES);
        }

        // ---- epilogue: bias + relu + store ----
#pragma unroll
        for (int nt = 0; nt < 4; ++nt) {
            const int o0 = wn * 32 + nt * 8 + 2 * tg;
            const float bz0 = __ldg(bias + o0), bz1 = __ldg(bias + o0 + 1);
            const size_t ob0 = ((size_t)n * O_DIM + o0) * W_DIM + w0;
            const size_t ob1 = ob0 + W_DIM;
#pragma unroll
            for (int mt = 0; mt < 2; ++mt) {
                const int wrow = wr * 32 + mt * 16 + g2;
                out[ob0 + wrow]     = fmaxf(acc[mt][nt][0] + bz0, 0.0f);
                out[ob1 + wrow]     = fmaxf(acc[mt][nt][1] + bz1, 0.0f);
                out[ob0 + wrow + 8] = fmaxf(acc[mt][nt][2] + bz0, 0.0f);
                out[ob1 + wrow + 8] = fmaxf(acc[mt][nt][3] + bz1, 0.0f);
            }
        }

        n = n2; w0 = w02; xHn = xHn2;
    }

    asm volatile("cp.async.wait_group 0;" ::: "memory");
    __syncthreads();
}

// ---------------------------------------------------------------------------
extern "C" void kernel_launch(void* const* d_in, const int* in_sizes, int n_in,
                              void* d_out, int out_size) {
    const float* input  = (const float*)d_in[0];
    const int*   tbl32  = (const int*)d_in[1];
    const float* weight = (const float*)d_in[2];
    const float* bias   = (const float*)d_in[3];
    float*       out    = (float*)d_out;

    cudaFuncSetAttribute(conv_kernel,
                         cudaFuncAttributeMaxDynamicSharedMemorySize, SMEM_BYTES);

    int dev = 0;
    cudaGetDevice(&dev);
    int nsm = 148;
    cudaDeviceGetAttribute(&nsm, cudaDevAttrMultiProcessorCount, dev);

    detect_kernel<<<1, 64>>>(tbl32);
    convert_kernel<<<(TBL_ELEMS + 255) / 256, 256>>>(tbl32);
    transpose_kernel<<<dim3(W_DIM / 32, C_DIM / 32, N_DIM), dim3(32, 8)>>>(input);
    wprep_kernel<<<(O_DIM * C_DIM * K_DIM + 255) / 256, 256>>>(weight);
    conv_kernel<<<2 * nsm, 256, SMEM_BYTES>>>(bias, out);
}

// round 16
// speedup vs baseline: 1.2627x; 1.0962x over previous
#include <cuda_runtime.h>
#include <cuda_fp16.h>
#include <cstdint>

#define W_DIM 81920
#define N_DIM 4
#define C_DIM 64
#define O_DIM 64
#define K_DIM 10
#define TILE_W 128
#define TILES_PER_N (W_DIM / TILE_W)            // 640
#define NTILES      (N_DIM * TILES_PER_N)       // 2560
#define TBL_ELEMS   (W_DIM * K_DIM)             // 819200
#define PHASES 10
#define A_STAGE 16384                           // 128 rows x 128 B, swizzled
#define WOFF    (2 * A_STAGE)                   // weights at 32768
#define W_SLICE 8192                            // 64 rows x 128 B per k
#define SMEM_BYTES (WOFF + K_DIM * W_SLICE)     // 114688

// Static device scratch (no runtime allocation)
__device__ __half g_xH[(size_t)N_DIM * W_DIM * C_DIM];  // [N,W,C] fp16
__device__ __half g_wH[K_DIM * O_DIM * C_DIM];          // [k][o][c] fp16
__device__ int    g_idxT[TBL_ELEMS];                    // gather table [k][w]

// ---------------------------------------------------------------------------
// Canonicalize conv_table -> int32 [k][w]. Dtype detected inline: genuine
// int64 (< 2^31) has all-zero odd 32-bit words; 8 odd words all zero under
// int32 index data has probability ~1e-39. All 8 reads are L2-broadcast hits.
// ---------------------------------------------------------------------------
__global__ void convert_kernel(const int* __restrict__ t32) {
    int probe = t32[1] | t32[3] | t32[5] | t32[7]
              | t32[9] | t32[11] | t32[13] | t32[15];
    bool is32 = (probe != 0);
    int i = blockIdx.x * 256 + threadIdx.x;
    if (i < TBL_ELEMS) {
        int v = is32 ? t32[i] : t32[2 * i];
        int w = i / K_DIM;
        int k = i - w * K_DIM;
        g_idxT[k * W_DIM + w] = v;
    }
}

// ---------------------------------------------------------------------------
// input [N,C,W] -> g_xH [N,W,C] fp16. Block: 64 w x 64 c (full C).
// Loads: warp-coherent float4 (256B full lines); smem [64][65] conflict-free;
// stores: uint4, 1KB contiguous per warp.
// ---------------------------------------------------------------------------
__global__ void transpose64_kernel(const float* __restrict__ in) {
    __shared__ float s[64][65];
    const int n  = blockIdx.y;
    const int w0 = blockIdx.x << 6;
    const int tid  = threadIdx.x;
    const int wrp  = tid >> 5;          // 0..7
    const int lane = tid & 31;
    const int lrow = lane >> 4;         // 0..1 (row within warp pair)
    const int lch  = lane & 15;         // float4 chunk 0..15

    // load 64 c-rows x 64 w (16 float4 each); warp covers 2 rows per pass
    const size_t inb = ((size_t)n * C_DIM) * W_DIM + w0;
#pragma unroll
    for (int pass = 0; pass < 4; ++pass) {
        int c = pass * 16 + wrp * 2 + lrow;
        float4 v = *reinterpret_cast<const float4*>(in + inb + (size_t)c * W_DIM + lch * 4);
        s[c][lch * 4 + 0] = v.x;
        s[c][lch * 4 + 1] = v.y;
        s[c][lch * 4 + 2] = v.z;
        s[c][lch * 4 + 3] = v.w;
    }
    __syncthreads();

    // store: w-row = tid>>2 (0..63), quarter q = tid&3 covers c = 16q..16q+15
    const int w = tid >> 2;
    const int q = tid & 3;
    unsigned r[8];
#pragma unroll
    for (int j = 0; j < 8; ++j) {
        __half2 h = __floats2half2_rn(s[q * 16 + 2 * j][w], s[q * 16 + 2 * j + 1][w]);
        r[j] = *reinterpret_cast<unsigned*>(&h);
    }
    uint4 o0 = make_uint4(r[0], r[1], r[2], r[3]);
    uint4 o1 = make_uint4(r[4], r[5], r[6], r[7]);
    const size_t ob = ((size_t)n * W_DIM + w0 + w) * C_DIM + q * 16;
    *reinterpret_cast<uint4*>(&g_xH[ob])     = o0;
    *reinterpret_cast<uint4*>(&g_xH[ob + 8]) = o1;
}

// weight [O,C,K,1] -> g_wH [k][o][c] (fp16)
__global__ void wprep_kernel(const float* __restrict__ w) {
    int i = blockIdx.x * 256 + threadIdx.x;
    if (i < O_DIM * C_DIM * K_DIM) {
        int o = i / (C_DIM * K_DIM);
        int r = i - o * (C_DIM * K_DIM);
        int c = r / K_DIM;
        int k = r - c * K_DIM;
        g_wH[(k * O_DIM + o) * C_DIM + c] = __float2half(w[i]);
    }
}

// ---------------------------------------------------------------------------
// Conv: tile 128w x 64o. Weights (80KB fp16, all k) resident in smem, XOR-
// swizzled 128B rows. A double-buffered 2x16KB swizzled stages via cp.async.
// fp16 mma.sync m16n8k16 f32-accum; 8 warps 4(m) x 2(n), warp tile 32x32.
// ---------------------------------------------------------------------------
__global__ void __launch_bounds__(256, 2)
conv_kernel(const float* __restrict__ bias, float* __restrict__ out) {
    extern __shared__ char smem[];
    const unsigned sb = (unsigned)__cvta_generic_to_shared(smem);

    const int tid  = threadIdx.x;
    const int wid  = tid >> 5;
    const int lane = tid & 31;
    const int wr   = wid >> 1;          // warp row 0..3 (m offset 32*wr)
    const int wn   = wid & 1;           // warp col 0..1 (n offset 32*wn)

    const int lr  = lane & 7;
    const int lm  = lane >> 3;
    const int ach = lm >> 1;            // A logical chunk base (16B units)
    const int bch = lm & 1;             // B logical chunk base
    unsigned arb[2]; int ars[2];
#pragma unroll
    for (int mt = 0; mt < 2; ++mt) {
        int row = wr * 32 + mt * 16 + (lm & 1) * 8 + lr;
        arb[mt] = (unsigned)(row << 7);
        ars[mt] = row & 7;
    }
    unsigned brb[2]; int brs[2];
#pragma unroll
    for (int bp = 0; bp < 2; ++bp) {
        int row = wn * 32 + bp * 16 + (lm >> 1) * 8 + lr;
        brb[bp] = (unsigned)(WOFF + (row << 7));
        brs[bp] = row & 7;
    }

    const int g2 = lane >> 2;
    const int tg = lane & 3;

    // one-time weight load: 5120 16B chunks, swizzled
#pragma unroll
    for (int it = 0; it < 20; ++it) {
        int lin = tid + 256 * it;
        int row = lin >> 3;
        int c   = lin & 7;
        unsigned dst = sb + (unsigned)(WOFF + (row << 7) + ((c ^ (row & 7)) << 4));
        const __half* src = g_wH + (row << 6) + c * 8;
        asm volatile("cp.async.cg.shared.global [%0], [%1], 16;"
                     :: "r"(dst), "l"(src) : "memory");
    }
    asm volatile("cp.async.commit_group;" ::: "memory");

    const int arow = tid >> 3;
    const int ac8  = tid & 7;
    const int axor = (arow & 7);

    // issue phase p of a tile into stage (p&1); index loads hoisted (MLP=4)
    auto issue = [&](const __half* xb, int w0_, int p) {
        const unsigned stg = sb + (unsigned)((p & 1) * A_STAGE);
        const int* idxp = g_idxT + p * W_DIM + w0_;
        const unsigned soff = (unsigned)((ac8 ^ axor) << 4);
        int idxs[4];
#pragma unroll
        for (int j = 0; j < 4; ++j)
            idxs[j] = __ldg(idxp + arow + 32 * j);
#pragma unroll
        for (int j = 0; j < 4; ++j) {
            int row = arow + 32 * j;
            unsigned sa = stg + (unsigned)(row << 7) + soff;
            const __half* ga = xb + (size_t)idxs[j] * C_DIM + ac8 * 8;
            asm volatile("cp.async.cg.shared.global [%0], [%1], 16;"
                         :: "r"(sa), "l"(ga) : "memory");
        }
        asm volatile("cp.async.commit_group;" ::: "memory");
    };

    int t  = blockIdx.x;
    int n  = t / TILES_PER_N;
    int w0 = (t - n * TILES_PER_N) * TILE_W;
    const __half* xHn = g_xH + (size_t)n * W_DIM * C_DIM;

    issue(xHn, w0, 0);
    issue(xHn, w0, 1);

    for (; t < NTILES; t += gridDim.x) {
        int t2  = t + gridDim.x; if (t2 >= NTILES) t2 = NTILES - 1;
        int n2  = t2 / TILES_PER_N;
        int w02 = (t2 - n2 * TILES_PER_N) * TILE_W;
        const __half* xHn2 = g_xH + (size_t)n2 * W_DIM * C_DIM;

        float acc[2][4][4];
#pragma unroll
        for (int mt = 0; mt < 2; ++mt)
#pragma unroll
            for (int nt = 0; nt < 4; ++nt)
#pragma unroll
                for (int r = 0; r < 4; ++r) acc[mt][nt][r] = 0.0f;

        for (int p = 0; p < PHASES; ++p) {
            asm volatile("cp.async.wait_group 1;" ::: "memory");
            __syncthreads();

            const unsigned stg  = sb + (unsigned)((p & 1) * A_STAGE);
            const unsigned wslc = (unsigned)(p * W_SLICE);
#pragma unroll
            for (int kk = 0; kk < 4; ++kk) {
                uint32_t a[2][4], b[4][2];
#pragma unroll
                for (int mt = 0; mt < 2; ++mt) {
                    unsigned ad = stg + arb[mt]
                                + (unsigned)((((ach + 2 * kk) ^ ars[mt])) << 4);
                    asm volatile(
                        "ldmatrix.sync.aligned.m8n8.x4.shared.b16 {%0,%1,%2,%3}, [%4];"
                        : "=r"(a[mt][0]), "=r"(a[mt][1]), "=r"(a[mt][2]), "=r"(a[mt][3])
                        : "r"(ad));
                }
#pragma unroll
                for (int bp = 0; bp < 2; ++bp) {
                    unsigned bd = sb + brb[bp] + wslc
                                + (unsigned)((((bch + 2 * kk) ^ brs[bp])) << 4);
                    asm volatile(
                        "ldmatrix.sync.aligned.m8n8.x4.shared.b16 {%0,%1,%2,%3}, [%4];"
                        : "=r"(b[2 * bp][0]), "=r"(b[2 * bp][1]),
                          "=r"(b[2 * bp + 1][0]), "=r"(b[2 * bp + 1][1])
                        : "r"(bd));
                }
#pragma unroll
                for (int mt = 0; mt < 2; ++mt)
#pragma unroll
                    for (int nt = 0; nt < 4; ++nt)
                        asm volatile(
                            "mma.sync.aligned.m16n8k16.row.col.f32.f16.f16.f32 "
                            "{%0,%1,%2,%3}, {%4,%5,%6,%7}, {%8,%9}, {%0,%1,%2,%3};"
                            : "+f"(acc[mt][nt][0]), "+f"(acc[mt][nt][1]),
                              "+f"(acc[mt][nt][2]), "+f"(acc[mt][nt][3])
                            : "r"(a[mt][0]), "r"(a[mt][1]), "r"(a[mt][2]), "r"(a[mt][3]),
                              "r"(b[nt][0]), "r"(b[nt][1]));
            }

            int q = p + 2;
            if (q < PHASES) issue(xHn, w0, q);
            else            issue(xHn2, w02, q - PHASES);
        }

        // epilogue: bias + relu + store
#pragma unroll
        for (int nt = 0; nt < 4; ++nt) {
            const int o0 = wn * 32 + nt * 8 + 2 * tg;
            const float bz0 = __ldg(bias + o0), bz1 = __ldg(bias + o0 + 1);
            const size_t ob0 = ((size_t)n * O_DIM + o0) * W_DIM + w0;
            const size_t ob1 = ob0 + W_DIM;
#pragma unroll
            for (int mt = 0; mt < 2; ++mt) {
                const int wrow = wr * 32 + mt * 16 + g2;
                out[ob0 + wrow]     = fmaxf(acc[mt][nt][0] + bz0, 0.0f);
                out[ob1 + wrow]     = fmaxf(acc[mt][nt][1] + bz1, 0.0f);
                out[ob0 + wrow + 8] = fmaxf(acc[mt][nt][2] + bz0, 0.0f);
                out[ob1 + wrow + 8] = fmaxf(acc[mt][nt][3] + bz1, 0.0f);
            }
        }

        n = n2; w0 = w02; xHn = xHn2;
    }

    asm volatile("cp.async.wait_group 0;" ::: "memory");
    __syncthreads();
}

// ---------------------------------------------------------------------------
extern "C" void kernel_launch(void* const* d_in, const int* in_sizes, int n_in,
                              void* d_out, int out_size) {
    const float* input  = (const float*)d_in[0];
    const int*   tbl32  = (const int*)d_in[1];
    const float* weight = (const float*)d_in[2];
    const float* bias   = (const float*)d_in[3];
    float*       out    = (float*)d_out;

    cudaFuncSetAttribute(conv_kernel,
                         cudaFuncAttributeMaxDynamicSharedMemorySize, SMEM_BYTES);

    int dev = 0;
    cudaGetDevice(&dev);
    int nsm = 148;
    cudaDeviceGetAttribute(&nsm, cudaDevAttrMultiProcessorCount, dev);

    convert_kernel<<<(TBL_ELEMS + 255) / 256, 256>>>(tbl32);
    transpose64_kernel<<<dim3(W_DIM / 64, N_DIM), 256>>>(input);
    wprep_kernel<<<(O_DIM * C_DIM * K_DIM + 255) / 256, 256>>>(weight);
    conv_kernel<<<2 * nsm, 256, SMEM_BYTES>>>(bias, out);
}

// round 17
// speedup vs baseline: 1.3116x; 1.0387x over previous
#include <cuda_runtime.h>
#include <cuda_fp16.h>
#include <cstdint>

#define W_DIM 81920
#define N_DIM 4
#define C_DIM 64
#define O_DIM 64
#define K_DIM 10
#define TILE_W 128
#define TILES_PER_N (W_DIM / TILE_W)            // 640
#define NTILES      (N_DIM * TILES_PER_N)       // 2560
#define TBL_ELEMS   (W_DIM * K_DIM)             // 819200
#define PHASES 10
#define A_STAGE 16384                           // 128 rows x 128 B, swizzled
#define WOFF    (2 * A_STAGE)                   // weights at 32768
#define W_SLICE 8192                            // 64 rows x 128 B per k
#define SMEM_BYTES (WOFF + K_DIM * W_SLICE)     // 114688

// fused prep grid layout
#define TR_BLOCKS   (W_DIM / 64 * N_DIM)        // 5120
#define CV_BLOCKS   ((TBL_ELEMS + 255) / 256)   // 3200
#define WP_BLOCKS   ((O_DIM * C_DIM * K_DIM + 255) / 256)  // 160
#define PREP_BLOCKS (TR_BLOCKS + CV_BLOCKS + WP_BLOCKS)    // 8480

// Static device scratch (no runtime allocation)
__device__ __half g_xH[(size_t)N_DIM * W_DIM * C_DIM];  // [N,W,C] fp16
__device__ __half g_wH[K_DIM * O_DIM * C_DIM];          // [k][o][c] fp16
__device__ int    g_idxT[TBL_ELEMS];                    // gather table [k][w]

// ---------------------------------------------------------------------------
// Fused prep: one launch, three jobs by blockIdx range.
//  [0, TR_BLOCKS)              input [N,C,W] -> g_xH [N,W,C] fp16
//  [TR_BLOCKS, +CV_BLOCKS)     conv_table -> int32 [k][w] (dtype auto-detect)
//  [TR_BLOCKS+CV_BLOCKS, ...)  weight [O,C,K,1] -> g_wH [k][o][c] fp16
// ---------------------------------------------------------------------------
__global__ void __launch_bounds__(256)
prep_kernel(const float* __restrict__ in,
            const int*   __restrict__ t32,
            const float* __restrict__ w) {
    const int bid = blockIdx.x;
    const int tid = threadIdx.x;

    if (bid < TR_BLOCKS) {
        // ---- transpose: block = 64 w x 64 c (full C) ----
        __shared__ float s[64][65];
        const int n  = bid / (W_DIM / 64);
        const int w0 = (bid - n * (W_DIM / 64)) << 6;
        const int wrp  = tid >> 5;
        const int lane = tid & 31;
        const int lrow = lane >> 4;
        const int lch  = lane & 15;

        const size_t inb = ((size_t)n * C_DIM) * W_DIM + w0;
#pragma unroll
        for (int pass = 0; pass < 4; ++pass) {
            int c = pass * 16 + wrp * 2 + lrow;
            float4 v = *reinterpret_cast<const float4*>(
                in + inb + (size_t)c * W_DIM + lch * 4);
            s[c][lch * 4 + 0] = v.x;
            s[c][lch * 4 + 1] = v.y;
            s[c][lch * 4 + 2] = v.z;
            s[c][lch * 4 + 3] = v.w;
        }
        __syncthreads();

        const int ww = tid >> 2;
        const int q  = tid & 3;
        unsigned r[8];
#pragma unroll
        for (int j = 0; j < 8; ++j) {
            __half2 h = __floats2half2_rn(s[q * 16 + 2 * j][ww],
                                          s[q * 16 + 2 * j + 1][ww]);
            r[j] = *reinterpret_cast<unsigned*>(&h);
        }
        uint4 o0 = make_uint4(r[0], r[1], r[2], r[3]);
        uint4 o1 = make_uint4(r[4], r[5], r[6], r[7]);
        const size_t ob = ((size_t)n * W_DIM + w0 + ww) * C_DIM + q * 16;
        *reinterpret_cast<uint4*>(&g_xH[ob])     = o0;
        *reinterpret_cast<uint4*>(&g_xH[ob + 8]) = o1;

    } else if (bid < TR_BLOCKS + CV_BLOCKS) {
        // ---- conv_table canonicalize (dtype detect: int64 has zero odd words;
        //      8 zero odd words under int32 data has probability ~1e-39) ----
        int probe = t32[1] | t32[3] | t32[5] | t32[7]
                  | t32[9] | t32[11] | t32[13] | t32[15];
        bool is32 = (probe != 0);
        int i = (bid - TR_BLOCKS) * 256 + tid;
        if (i < TBL_ELEMS) {
            int v  = is32 ? t32[i] : t32[2 * i];
            int ww = i / K_DIM;
            int k  = i - ww * K_DIM;
            g_idxT[k * W_DIM + ww] = v;
        }

    } else {
        // ---- weight [O,C,K,1] -> g_wH [k][o][c] fp16 ----
        int i = (bid - TR_BLOCKS - CV_BLOCKS) * 256 + tid;
        if (i < O_DIM * C_DIM * K_DIM) {
            int o = i / (C_DIM * K_DIM);
            int r = i - o * (C_DIM * K_DIM);
            int c = r / K_DIM;
            int k = r - c * K_DIM;
            g_wH[(k * O_DIM + o) * C_DIM + c] = __float2half(w[i]);
        }
    }
}

// ---------------------------------------------------------------------------
// Conv: tile 128w x 64o. Weights (80KB fp16, all k) resident in smem, XOR-
// swizzled 128B rows. A double-buffered 2x16KB swizzled stages via cp.async.
// fp16 mma.sync m16n8k16 f32-accum; 8 warps 4(m) x 2(n), warp tile 32x32.
// (Byte-identical to the validated 95.9us R16 kernel.)
// ---------------------------------------------------------------------------
__global__ void __launch_bounds__(256, 2)
conv_kernel(const float* __restrict__ bias, float* __restrict__ out) {
    extern __shared__ char smem[];
    const unsigned sb = (unsigned)__cvta_generic_to_shared(smem);

    const int tid  = threadIdx.x;
    const int wid  = tid >> 5;
    const int lane = tid & 31;
    const int wr   = wid >> 1;          // warp row 0..3 (m offset 32*wr)
    const int wn   = wid & 1;           // warp col 0..1 (n offset 32*wn)

    const int lr  = lane & 7;
    const int lm  = lane >> 3;
    const int ach = lm >> 1;            // A logical chunk base (16B units)
    const int bch = lm & 1;             // B logical chunk base
    unsigned arb[2]; int ars[2];
#pragma unroll
    for (int mt = 0; mt < 2; ++mt) {
        int row = wr * 32 + mt * 16 + (lm & 1) * 8 + lr;
        arb[mt] = (unsigned)(row << 7);
        ars[mt] = row & 7;
    }
    unsigned brb[2]; int brs[2];
#pragma unroll
    for (int bp = 0; bp < 2; ++bp) {
        int row = wn * 32 + bp * 16 + (lm >> 1) * 8 + lr;
        brb[bp] = (unsigned)(WOFF + (row << 7));
        brs[bp] = row & 7;
    }

    const int g2 = lane >> 2;
    const int tg = lane & 3;

    // one-time weight load: 5120 16B chunks, swizzled
#pragma unroll
    for (int it = 0; it < 20; ++it) {
        int lin = tid + 256 * it;
        int row = lin >> 3;
        int c   = lin & 7;
        unsigned dst = sb + (unsigned)(WOFF + (row << 7) + ((c ^ (row & 7)) << 4));
        const __half* src = g_wH + (row << 6) + c * 8;
        asm volatile("cp.async.cg.shared.global [%0], [%1], 16;"
                     :: "r"(dst), "l"(src) : "memory");
    }
    asm volatile("cp.async.commit_group;" ::: "memory");

    const int arow = tid >> 3;
    const int ac8  = tid & 7;
    const int axor = (arow & 7);

    auto issue = [&](const __half* xb, int w0_, int p) {
        const unsigned stg = sb + (unsigned)((p & 1) * A_STAGE);
        const int* idxp = g_idxT + p * W_DIM + w0_;
        const unsigned soff = (unsigned)((ac8 ^ axor) << 4);
        int idxs[4];
#pragma unroll
        for (int j = 0; j < 4; ++j)
            idxs[j] = __ldg(idxp + arow + 32 * j);
#pragma unroll
        for (int j = 0; j < 4; ++j) {
            int row = arow + 32 * j;
            unsigned sa = stg + (unsigned)(row << 7) + soff;
            const __half* ga = xb + (size_t)idxs[j] * C_DIM + ac8 * 8;
            asm volatile("cp.async.cg.shared.global [%0], [%1], 16;"
                         :: "r"(sa), "l"(ga) : "memory");
        }
        asm volatile("cp.async.commit_group;" ::: "memory");
    };

    int t  = blockIdx.x;
    int n  = t / TILES_PER_N;
    int w0 = (t - n * TILES_PER_N) * TILE_W;
    const __half* xHn = g_xH + (size_t)n * W_DIM * C_DIM;

    issue(xHn, w0, 0);
    issue(xHn, w0, 1);

    for (; t < NTILES; t += gridDim.x) {
        int t2  = t + gridDim.x; if (t2 >= NTILES) t2 = NTILES - 1;
        int n2  = t2 / TILES_PER_N;
        int w02 = (t2 - n2 * TILES_PER_N) * TILE_W;
        const __half* xHn2 = g_xH + (size_t)n2 * W_DIM * C_DIM;

        float acc[2][4][4];
#pragma unroll
        for (int mt = 0; mt < 2; ++mt)
#pragma unroll
            for (int nt = 0; nt < 4; ++nt)
#pragma unroll
                for (int r = 0; r < 4; ++r) acc[mt][nt][r] = 0.0f;

        for (int p = 0; p < PHASES; ++p) {
            asm volatile("cp.async.wait_group 1;" ::: "memory");
            __syncthreads();

            const unsigned stg  = sb + (unsigned)((p & 1) * A_STAGE);
            const unsigned wslc = (unsigned)(p * W_SLICE);
#pragma unroll
            for (int kk = 0; kk < 4; ++kk) {
                uint32_t a[2][4], b[4][2];
#pragma unroll
                for (int mt = 0; mt < 2; ++mt) {
                    unsigned ad = stg + arb[mt]
                                + (unsigned)((((ach + 2 * kk) ^ ars[mt])) << 4);
                    asm volatile(
                        "ldmatrix.sync.aligned.m8n8.x4.shared.b16 {%0,%1,%2,%3}, [%4];"
                        : "=r"(a[mt][0]), "=r"(a[mt][1]), "=r"(a[mt][2]), "=r"(a[mt][3])
                        : "r"(ad));
                }
#pragma unroll
                for (int bp = 0; bp < 2; ++bp) {
                    unsigned bd = sb + brb[bp] + wslc
                                + (unsigned)((((bch + 2 * kk) ^ brs[bp])) << 4);
                    asm volatile(
                        "ldmatrix.sync.aligned.m8n8.x4.shared.b16 {%0,%1,%2,%3}, [%4];"
                        : "=r"(b[2 * bp][0]), "=r"(b[2 * bp][1]),
                          "=r"(b[2 * bp + 1][0]), "=r"(b[2 * bp + 1][1])
                        : "r"(bd));
                }
#pragma unroll
                for (int mt = 0; mt < 2; ++mt)
#pragma unroll
                    for (int nt = 0; nt < 4; ++nt)
                        asm volatile(
                            "mma.sync.aligned.m16n8k16.row.col.f32.f16.f16.f32 "
                            "{%0,%1,%2,%3}, {%4,%5,%6,%7}, {%8,%9}, {%0,%1,%2,%3};"
                            : "+f"(acc[mt][nt][0]), "+f"(acc[mt][nt][1]),
                              "+f"(acc[mt][nt][2]), "+f"(acc[mt][nt][3])
                            : "r"(a[mt][0]), "r"(a[mt][1]), "r"(a[mt][2]), "r"(a[mt][3]),
                              "r"(b[nt][0]), "r"(b[nt][1]));
            }

            int q = p + 2;
            if (q < PHASES) issue(xHn, w0, q);
            else            issue(xHn2, w02, q - PHASES);
        }

        // epilogue: bias + relu + store
#pragma unroll
        for (int nt = 0; nt < 4; ++nt) {
            const int o0 = wn * 32 + nt * 8 + 2 * tg;
            const float bz0 = __ldg(bias + o0), bz1 = __ldg(bias + o0 + 1);
            const size_t ob0 = ((size_t)n * O_DIM + o0) * W_DIM + w0;
            const size_t ob1 = ob0 + W_DIM;
#pragma unroll
            for (int mt = 0; mt < 2; ++mt) {
                const int wrow = wr * 32 + mt * 16 + g2;
                out[ob0 + wrow]     = fmaxf(acc[mt][nt][0] + bz0, 0.0f);
                out[ob1 + wrow]     = fmaxf(acc[mt][nt][1] + bz1, 0.0f);
                out[ob0 + wrow + 8] = fmaxf(acc[mt][nt][2] + bz0, 0.0f);
                out[ob1 + wrow + 8] = fmaxf(acc[mt][nt][3] + bz1, 0.0f);
            }
        }

        n = n2; w0 = w02; xHn = xHn2;
    }

    asm volatile("cp.async.wait_group 0;" ::: "memory");
    __syncthreads();
}

// ---------------------------------------------------------------------------
extern "C" void kernel_launch(void* const* d_in, const int* in_sizes, int n_in,
                              void* d_out, int out_size) {
    const float* input  = (const float*)d_in[0];
    const int*   tbl32  = (const int*)d_in[1];
    const float* weight = (const float*)d_in[2];
    const float* bias   = (const float*)d_in[3];
    float*       out    = (float*)d_out;

    cudaFuncSetAttribute(conv_kernel,
                         cudaFuncAttributeMaxDynamicSharedMemorySize, SMEM_BYTES);

    int dev = 0;
    cudaGetDevice(&dev);
    int nsm = 148;
    cudaDeviceGetAttribute(&nsm, cudaDevAttrMultiProcessorCount, dev);

    prep_kernel<<<PREP_BLOCKS, 256>>>(input, tbl32, weight);
    conv_kernel<<<2 * nsm, 256, SMEM_BYTES>>>(bias, out);
}